// round 5
// baseline (speedup 1.0000x reference)
#include <cuda_runtime.h>
#include <math.h>

// Problem dims (fixed by reference)
#define T_DIM    8192
#define OBS_DIM  512
#define HID_DIM  2048
#define NOBJ_DIM 8
#define SEG      (T_DIM * HID_DIM)      // 16,777,216 elements per [T,HID] plane
#define NCHUNK   64
#define CHUNK_L  (T_DIM / NCHUNK)       // 128

// ---------------------------------------------------------------------------
// Scratch: __device__ globals (no dynamic allocation allowed anywhere).
//   g_gemm: 4 planes [type][t][h]; type 0=x_state, 1=B, 2=C, 3=delta_pre
// ---------------------------------------------------------------------------
__device__ float g_gemm[4 * SEG];               // 256 MB
__device__ float g_a [SEG];                     // per-step decay A_bar
__device__ float g_bx[SEG];                     // per-step input B*x_state
__device__ float g_y [SEG];                     // C * h_seq
__device__ float g_ca   [NCHUNK * HID_DIM];     // chunk aggregate: prod(a)
__device__ float g_cb   [NCHUNK * HID_DIM];     // chunk aggregate: scan-from-0
__device__ float g_hinit[NCHUNK * HID_DIM];     // carry-in state per chunk

// ---------------------------------------------------------------------------
// Kernel 1: SGEMM (NT): C[m,n] = sum_k A[m,k] * W[n,k]
//   A = x [8192,512] row-major, W [2048,512] row-major (both K-contiguous).
//   128x128 tile, BK=16, 8x8 microtile, 256 threads, double-buffered smem.
//   Writes into g_gemm[type] with ldc = HID_DIM.
// ---------------------------------------------------------------------------
__global__ __launch_bounds__(256, 2) void sgemm_nt(const float* __restrict__ A,
                                                   const float* __restrict__ W,
                                                   int type)
{
    __shared__ float As[2][16][128];
    __shared__ float Bs[2][16][128];

    const int tid = threadIdx.x;
    const int tx  = tid & 15;          // 0..15 -> n microtile
    const int ty  = tid >> 4;          // 0..15 -> m microtile
    const int m0  = blockIdx.y * 128;
    const int n0  = blockIdx.x * 128;

    // Global-load mapping: 128 rows x 4 float4 per row; each thread 2 rows.
    const int lrow = tid >> 2;          // 0..63
    const int lcol = (tid & 3) << 2;    // 0,4,8,12

    const float* Ag = A + (size_t)(m0 + lrow) * OBS_DIM + lcol;
    const float* Wg = W + (size_t)(n0 + lrow) * OBS_DIM + lcol;

    float4 ra0 = *(const float4*)(Ag);
    float4 ra1 = *(const float4*)(Ag + 64 * OBS_DIM);
    float4 rb0 = *(const float4*)(Wg);
    float4 rb1 = *(const float4*)(Wg + 64 * OBS_DIM);

    {
        const float* pa0 = (const float*)&ra0;
        const float* pa1 = (const float*)&ra1;
        const float* pb0 = (const float*)&rb0;
        const float* pb1 = (const float*)&rb1;
#pragma unroll
        for (int i = 0; i < 4; i++) {
            As[0][lcol + i][lrow]      = pa0[i];
            As[0][lcol + i][lrow + 64] = pa1[i];
            Bs[0][lcol + i][lrow]      = pb0[i];
            Bs[0][lcol + i][lrow + 64] = pb1[i];
        }
    }
    __syncthreads();

    float acc[8][8];
#pragma unroll
    for (int i = 0; i < 8; i++)
#pragma unroll
        for (int j = 0; j < 8; j++) acc[i][j] = 0.0f;

    const int NT = OBS_DIM / 16;  // 32 k-tiles
    for (int kt = 0; kt < NT; kt++) {
        const int cur = kt & 1;

        // Prefetch next k-tile from global into registers (lands during compute)
        if (kt + 1 < NT) {
            const float* Ag2 = Ag + (kt + 1) * 16;
            const float* Wg2 = Wg + (kt + 1) * 16;
            ra0 = *(const float4*)(Ag2);
            ra1 = *(const float4*)(Ag2 + 64 * OBS_DIM);
            rb0 = *(const float4*)(Wg2);
            rb1 = *(const float4*)(Wg2 + 64 * OBS_DIM);
        }

#pragma unroll
        for (int kk = 0; kk < 16; kk++) {
            float af[8], bf[8];
            *(float4*)&af[0] = *(const float4*)&As[cur][kk][ty * 8];
            *(float4*)&af[4] = *(const float4*)&As[cur][kk][ty * 8 + 4];
            *(float4*)&bf[0] = *(const float4*)&Bs[cur][kk][tx * 8];
            *(float4*)&bf[4] = *(const float4*)&Bs[cur][kk][tx * 8 + 4];
#pragma unroll
            for (int i = 0; i < 8; i++)
#pragma unroll
                for (int j = 0; j < 8; j++)
                    acc[i][j] = fmaf(af[i], bf[j], acc[i][j]);
        }

        if (kt + 1 < NT) {
            const int nxt = cur ^ 1;
            const float* pa0 = (const float*)&ra0;
            const float* pa1 = (const float*)&ra1;
            const float* pb0 = (const float*)&rb0;
            const float* pb1 = (const float*)&rb1;
#pragma unroll
            for (int i = 0; i < 4; i++) {
                As[nxt][lcol + i][lrow]      = pa0[i];
                As[nxt][lcol + i][lrow + 64] = pa1[i];
                Bs[nxt][lcol + i][lrow]      = pb0[i];
                Bs[nxt][lcol + i][lrow + 64] = pb1[i];
            }
            __syncthreads();
        }
    }

    float* Cout = g_gemm + (size_t)type * SEG;
#pragma unroll
    for (int i = 0; i < 8; i++) {
        float4 v0 = make_float4(acc[i][0], acc[i][1], acc[i][2], acc[i][3]);
        float4 v1 = make_float4(acc[i][4], acc[i][5], acc[i][6], acc[i][7]);
        float* dst = Cout + (size_t)(m0 + ty * 8 + i) * HID_DIM + n0 + tx * 8;
        *(float4*)(dst)     = v0;
        *(float4*)(dst + 4) = v1;
    }
}

// ---------------------------------------------------------------------------
// Kernel 2: elementwise — a = exp(sigmoid(dl) * (-exp(A_log[h]))), bx = B*xs
// ---------------------------------------------------------------------------
__global__ __launch_bounds__(256) void elemwise_k(const float* __restrict__ A_log)
{
    const int i = (blockIdx.x * 256 + threadIdx.x) << 2;  // element index, vec4
    float4 xs = *(const float4*)&g_gemm[i];
    float4 Bv = *(const float4*)&g_gemm[SEG + i];
    float4 dl = *(const float4*)&g_gemm[3 * SEG + i];
    const int h = i & (HID_DIM - 1);

    float4 av, bv;
    const float* pxs = (const float*)&xs;
    const float* pB  = (const float*)&Bv;
    const float* pdl = (const float*)&dl;
    float* pav = (float*)&av;
    float* pbv = (float*)&bv;
#pragma unroll
    for (int c = 0; c < 4; c++) {
        float delta = 1.0f / (1.0f + expf(-pdl[c]));
        float negA  = -expf(A_log[h + c]);
        pav[c] = expf(delta * negA);
        pbv[c] = pB[c] * pxs[c];
    }
    *(float4*)&g_a [i] = av;
    *(float4*)&g_bx[i] = bv;
}

// ---------------------------------------------------------------------------
// Kernel 3: per-chunk aggregates.  For each (chunk, channel):
//   ap = prod a, bs = scan result starting from h=0.
// ---------------------------------------------------------------------------
__global__ __launch_bounds__(256) void chunk_reduce_k()
{
    const int h     = blockIdx.x * 256 + threadIdx.x;
    const int chunk = blockIdx.y;
    int idx = chunk * CHUNK_L * HID_DIM + h;

    float ap = 1.0f, bs = 0.0f;
#pragma unroll 8
    for (int l = 0; l < CHUNK_L; l++) {
        float a = g_a[idx];
        float b = g_bx[idx];
        bs = fmaf(a, bs, b);
        ap *= a;
        idx += HID_DIM;
    }
    g_ca[chunk * HID_DIM + h] = ap;
    g_cb[chunk * HID_DIM + h] = bs;
}

// ---------------------------------------------------------------------------
// Kernel 4: exclusive prefix over chunk aggregates -> carry-in state per chunk.
// ---------------------------------------------------------------------------
__global__ __launch_bounds__(256) void chunk_prefix_k()
{
    const int h = blockIdx.x * 256 + threadIdx.x;
    float hc = 0.0f;
#pragma unroll
    for (int j = 0; j < NCHUNK; j++) {
        g_hinit[j * HID_DIM + h] = hc;
        hc = fmaf(g_ca[j * HID_DIM + h], hc, g_cb[j * HID_DIM + h]);
    }
}

// ---------------------------------------------------------------------------
// Kernel 5: second scan pass with carry-in, emit y = C * h.
// ---------------------------------------------------------------------------
__global__ __launch_bounds__(256) void scan2_k()
{
    const int h     = blockIdx.x * 256 + threadIdx.x;
    const int chunk = blockIdx.y;
    int idx = chunk * CHUNK_L * HID_DIM + h;

    float hc = g_hinit[chunk * HID_DIM + h];
    const float* gC = g_gemm + 2 * SEG;
#pragma unroll 4
    for (int l = 0; l < CHUNK_L; l++) {
        float a = g_a[idx];
        float b = g_bx[idx];
        hc = fmaf(a, hc, b);
        g_y[idx] = gC[idx] * hc;
        idx += HID_DIM;
    }
}

// ---------------------------------------------------------------------------
// Kernel 6: out[t,o] = y[t,:]·W_out[o,:] + b_out[o] + x[t,:]·W_skip[o,:]
// One block (256 threads) per timestep; warp + smem reduction.
// ---------------------------------------------------------------------------
__global__ __launch_bounds__(256) void outproj_k(const float* __restrict__ x,
                                                 const float* __restrict__ W_out,
                                                 const float* __restrict__ b_out,
                                                 const float* __restrict__ W_skip,
                                                 float* __restrict__ out)
{
    const int t   = blockIdx.x;
    const int tid = threadIdx.x;

    float acc[NOBJ_DIM];
#pragma unroll
    for (int o = 0; o < NOBJ_DIM; o++) acc[o] = 0.0f;

    const float* yr = g_y + (size_t)t * HID_DIM;
    for (int h = tid; h < HID_DIM; h += 256) {
        float yv = yr[h];
#pragma unroll
        for (int o = 0; o < NOBJ_DIM; o++)
            acc[o] = fmaf(yv, W_out[o * HID_DIM + h], acc[o]);
    }
    const float* xr = x + (size_t)t * OBS_DIM;
    for (int k = tid; k < OBS_DIM; k += 256) {
        float xv = xr[k];
#pragma unroll
        for (int o = 0; o < NOBJ_DIM; o++)
            acc[o] = fmaf(xv, W_skip[o * OBS_DIM + k], acc[o]);
    }

    // intra-warp reduce
#pragma unroll
    for (int o = 0; o < NOBJ_DIM; o++) {
#pragma unroll
        for (int off = 16; off > 0; off >>= 1)
            acc[o] += __shfl_xor_sync(0xffffffffu, acc[o], off);
    }

    __shared__ float sred[NOBJ_DIM][8];
    const int wid  = tid >> 5;
    const int lane = tid & 31;
    if (lane == 0) {
#pragma unroll
        for (int o = 0; o < NOBJ_DIM; o++) sred[o][wid] = acc[o];
    }
    __syncthreads();
    if (tid < NOBJ_DIM) {
        float s = b_out[tid];
#pragma unroll
        for (int w = 0; w < 8; w++) s += sred[tid][w];
        out[(size_t)t * NOBJ_DIM + tid] = s;
    }
}

// ---------------------------------------------------------------------------
// Launch: 4 GEMMs -> elementwise -> chunked scan (3 phases) -> out projection
// ---------------------------------------------------------------------------
extern "C" void kernel_launch(void* const* d_in, const int* in_sizes, int n_in,
                              void* d_out, int out_size)
{
    const float* x       = (const float*)d_in[0];
    const float* W_in    = (const float*)d_in[1];
    const float* W_B     = (const float*)d_in[2];
    const float* W_C     = (const float*)d_in[3];
    const float* W_delta = (const float*)d_in[4];
    const float* A_log   = (const float*)d_in[5];
    const float* W_out   = (const float*)d_in[6];
    const float* b_out   = (const float*)d_in[7];
    const float* W_skip  = (const float*)d_in[8];
    float* out = (float*)d_out;

    dim3 gemmGrid(HID_DIM / 128, T_DIM / 128);   // (16, 64)
    sgemm_nt<<<gemmGrid, 256>>>(x, W_in,    0);
    sgemm_nt<<<gemmGrid, 256>>>(x, W_B,     1);
    sgemm_nt<<<gemmGrid, 256>>>(x, W_C,     2);
    sgemm_nt<<<gemmGrid, 256>>>(x, W_delta, 3);

    elemwise_k<<<SEG / 4 / 256, 256>>>(A_log);

    chunk_reduce_k<<<dim3(HID_DIM / 256, NCHUNK), 256>>>();
    chunk_prefix_k<<<HID_DIM / 256, 256>>>();
    scan2_k<<<dim3(HID_DIM / 256, NCHUNK), 256>>>();

    outproj_k<<<T_DIM, 256>>>(x, W_out, b_out, W_skip, out);
}

// round 7
// speedup vs baseline: 1.9872x; 1.9872x over previous
#include <cuda_runtime.h>
#include <cuda_bf16.h>
#include <math.h>
#include <stdint.h>

// Problem dims (fixed by reference)
#define T_DIM    8192
#define OBS_DIM  512
#define HID_DIM  2048
#define NOBJ_DIM 8
#define SEG      (T_DIM * HID_DIM)
#define NCHUNK   64
#define CHUNK_L  (T_DIM / NCHUNK)       // 128

// ---------------------------------------------------------------------------
// Scratch (__device__ globals — no dynamic allocation allowed)
// ---------------------------------------------------------------------------
__device__ float g_gemm[4 * SEG];               // 0=x_state 1=B 2=C 3=delta_pre
__device__ float g_a [SEG];
__device__ float g_bx[SEG];
__device__ float g_y [SEG];
__device__ float g_ca   [NCHUNK * HID_DIM];
__device__ float g_cb   [NCHUNK * HID_DIM];
__device__ float g_hinit[NCHUNK * HID_DIM];

__device__ __nv_bfloat16 g_xhi[T_DIM * OBS_DIM];
__device__ __nv_bfloat16 g_xlo[T_DIM * OBS_DIM];
__device__ __nv_bfloat16 g_whi[4 * HID_DIM * OBS_DIM];
__device__ __nv_bfloat16 g_wlo[4 * HID_DIM * OBS_DIM];

// ---------------------------------------------------------------------------
// Helpers (NO 'a'-feature PTX: mma.sync / ldmatrix / cp.async only)
// ---------------------------------------------------------------------------
__device__ __forceinline__ uint32_t smem_to_u32(const void* p) {
    uint32_t a;
    asm("{ .reg .u64 t; cvta.to.shared.u64 t, %1; cvt.u32.u64 %0, t; }"
        : "=r"(a) : "l"(p));
    return a;
}

#define CP_ASYNC16(dst_u32, src_ptr) \
    asm volatile("cp.async.cg.shared.global [%0], [%1], 16;" \
                 :: "r"(dst_u32), "l"(src_ptr) : "memory")
#define CP_COMMIT() asm volatile("cp.async.commit_group;" ::: "memory")

#define LDSM4(r, addr) \
    asm volatile("ldmatrix.sync.aligned.m8n8.x4.shared.b16 {%0,%1,%2,%3}, [%4];" \
                 : "=r"((r)[0]), "=r"((r)[1]), "=r"((r)[2]), "=r"((r)[3]) \
                 : "r"(addr))

#define MMA16816(d, a, b) \
    asm volatile("mma.sync.aligned.m16n8k16.row.col.f32.bf16.bf16.f32 " \
                 "{%0,%1,%2,%3},{%4,%5,%6,%7},{%8,%9},{%0,%1,%2,%3};" \
                 : "+f"((d)[0]), "+f"((d)[1]), "+f"((d)[2]), "+f"((d)[3]) \
                 : "r"((a)[0]), "r"((a)[1]), "r"((a)[2]), "r"((a)[3]), \
                   "r"((b)[0]), "r"((b)[1]))

// ---------------------------------------------------------------------------
// Conversion: fp32 -> (hi, lo) bf16 split
// ---------------------------------------------------------------------------
__device__ __forceinline__ void split4(const float4 v, __nv_bfloat16* h, __nv_bfloat16* l) {
    const float* p = (const float*)&v;
#pragma unroll
    for (int c = 0; c < 4; c++) {
        __nv_bfloat16 hi = __float2bfloat16(p[c]);
        h[c] = hi;
        l[c] = __float2bfloat16(p[c] - __bfloat162float(hi));
    }
}

__global__ __launch_bounds__(256) void conv_x_k(const float* __restrict__ x) {
    const int i = (blockIdx.x * 256 + threadIdx.x) << 2;
    __nv_bfloat16 h[4], l[4];
    split4(*(const float4*)(x + i), h, l);
    *(uint2*)&g_xhi[i] = *(uint2*)h;
    *(uint2*)&g_xlo[i] = *(uint2*)l;
}

__global__ __launch_bounds__(256) void conv_w_k(const float* __restrict__ w0,
                                                const float* __restrict__ w1,
                                                const float* __restrict__ w2,
                                                const float* __restrict__ w3) {
    const int type = blockIdx.y;
    const float* w = (type == 0) ? w0 : (type == 1) ? w1 : (type == 2) ? w2 : w3;
    const int i = (blockIdx.x * 256 + threadIdx.x) << 2;
    __nv_bfloat16 h[4], l[4];
    split4(*(const float4*)(w + i), h, l);
    const int o = type * HID_DIM * OBS_DIM + i;
    *(uint2*)&g_whi[o] = *(uint2*)h;
    *(uint2*)&g_wlo[o] = *(uint2*)l;
}

// ---------------------------------------------------------------------------
// Split-bf16 GEMM via mma.sync:  g_gemm[type][m,n] = sum_k x[m,k]*W[type][n,k]
//   D = Ahi*Bhi + Ahi*Blo + Alo*Bhi   (fp32 accum; ll term dropped, ~2^-18)
// Tile 128x128xBK32, 8 warps (2x4), warp tile 64x32. cp.async double buffer.
// Smem rows padded to 80B -> conflict-free ldmatrix (5r+c distinct mod 8).
// ---------------------------------------------------------------------------
#define BM 128
#define BN 128
#define BK 32
#define RS 80                            // smem row stride (bytes)
#define PLANE_B (128 * RS)               // 10240 per plane
#define STAGE_B (4 * PLANE_B)            // 40960: Ahi|Alo|Bhi|Blo
#define GEMM_SMEM (2 * STAGE_B)          // 81920
#define KITERS (OBS_DIM / BK)            // 16

__global__ __launch_bounds__(256) void mma_gemm()
{
    extern __shared__ char smem[];
    const uint32_t sb = smem_to_u32(smem);
    const int tid   = threadIdx.x;
    const int lane  = tid & 31;
    const int wid   = tid >> 5;
    const int warpM = wid & 1;           // 0..1 -> 64-row half
    const int warpN = wid >> 1;          // 0..3 -> 32-col quarter
    const int n0    = blockIdx.x * BN;
    const int m0    = blockIdx.y * BM;
    const int type  = blockIdx.z;

    // Global sources (bf16, row-major, 512 K-contiguous)
    const __nv_bfloat16* srcAhi = g_xhi + (size_t)m0 * OBS_DIM;
    const __nv_bfloat16* srcAlo = g_xlo + (size_t)m0 * OBS_DIM;
    const size_t wbase = ((size_t)type * HID_DIM + n0) * OBS_DIM;
    const __nv_bfloat16* srcBhi = g_whi + wbase;
    const __nv_bfloat16* srcBlo = g_wlo + wbase;

    // cp.async mapping: idx = tid + j*256 -> row = idx>>2 (0..127), c = idx&3
    const int r0c = (tid >> 2);
    const int c0c = (tid & 3);

    float acc[4][4][4];
#pragma unroll
    for (int i = 0; i < 4; i++)
#pragma unroll
        for (int j = 0; j < 4; j++)
#pragma unroll
            for (int k = 0; k < 4; k++) acc[i][j][k] = 0.0f;

    // ldmatrix per-lane offsets
    const uint32_t aoff = (uint32_t)(lane & 15) * RS + (uint32_t)(lane >> 4) * 16;
    const uint32_t boff = (uint32_t)((lane >> 4) * 8 + (lane & 7)) * RS
                        + (uint32_t)((lane >> 3) & 1) * 16;
    const uint32_t aBase = sb + (uint32_t)(warpM * 64) * RS + aoff;
    const uint32_t bBase = sb + 2 * PLANE_B + (uint32_t)(warpN * 32) * RS + boff;

#define ISSUE_STAGE(kt, stage) do {                                              \
    const int _ko = (kt) * BK;                                                   \
    _Pragma("unroll")                                                            \
    for (int j = 0; j < 2; j++) {                                                \
        const int r = r0c + j * 64;                                              \
        const size_t gsrc = (size_t)r * OBS_DIM + _ko + c0c * 8;                 \
        const uint32_t d = sb + (stage) * STAGE_B + (uint32_t)r * RS + c0c * 16; \
        CP_ASYNC16(d,               srcAhi + gsrc);                              \
        CP_ASYNC16(d + PLANE_B,     srcAlo + gsrc);                              \
        CP_ASYNC16(d + 2 * PLANE_B, srcBhi + gsrc);                              \
        CP_ASYNC16(d + 3 * PLANE_B, srcBlo + gsrc);                              \
    }                                                                            \
} while (0)

    ISSUE_STAGE(0, 0);
    CP_COMMIT();

    for (int kt = 0; kt < KITERS; kt++) {
        if (kt + 1 < KITERS) {
            ISSUE_STAGE(kt + 1, (kt + 1) & 1);
            CP_COMMIT();
            asm volatile("cp.async.wait_group 1;" ::: "memory");
        } else {
            asm volatile("cp.async.wait_group 0;" ::: "memory");
        }
        __syncthreads();

        const uint32_t st = (uint32_t)(kt & 1) * STAGE_B;
#pragma unroll
        for (int ks = 0; ks < 2; ks++) {
            const uint32_t kb = (uint32_t)ks * 32;     // k16 step = 32 bytes

            uint32_t ah[4][4], al[4][4], bh[4][2], bl[4][2];
#pragma unroll
            for (int mt = 0; mt < 4; mt++) {
                const uint32_t a0 = aBase + st + (uint32_t)(mt * 16) * RS + kb;
                LDSM4(ah[mt], a0);
                LDSM4(al[mt], a0 + PLANE_B);
            }
#pragma unroll
            for (int ntp = 0; ntp < 2; ntp++) {
                const uint32_t b0 = bBase + st + (uint32_t)(ntp * 16) * RS + kb;
                uint32_t t0[4], t1[4];
                LDSM4(t0, b0);
                LDSM4(t1, b0 + PLANE_B);
                bh[2 * ntp][0] = t0[0]; bh[2 * ntp][1] = t0[1];
                bh[2 * ntp + 1][0] = t0[2]; bh[2 * ntp + 1][1] = t0[3];
                bl[2 * ntp][0] = t1[0]; bl[2 * ntp][1] = t1[1];
                bl[2 * ntp + 1][0] = t1[2]; bl[2 * ntp + 1][1] = t1[3];
            }

#pragma unroll
            for (int mt = 0; mt < 4; mt++)
#pragma unroll
                for (int nt = 0; nt < 4; nt++) {
                    MMA16816(acc[mt][nt], ah[mt], bh[nt]);
                    MMA16816(acc[mt][nt], ah[mt], bl[nt]);
                    MMA16816(acc[mt][nt], al[mt], bh[nt]);
                }
        }
        __syncthreads();   // protect buffer (kt&1) before next issue overwrites it
    }
#undef ISSUE_STAGE

    // Epilogue: c frag layout — c0,c1 at (row = l/4, col = (l%4)*2+{0,1}), c2,c3 row+8
    float* Cout = g_gemm + (size_t)type * SEG;
    const int mw = m0 + warpM * 64;
    const int nw = n0 + warpN * 32;
#pragma unroll
    for (int mt = 0; mt < 4; mt++) {
#pragma unroll
        for (int nt = 0; nt < 4; nt++) {
            const int rr = mw + mt * 16 + (lane >> 2);
            const int cc = nw + nt * 8 + (lane & 3) * 2;
            *(float2*)(Cout + (size_t)rr * HID_DIM + cc) =
                make_float2(acc[mt][nt][0], acc[mt][nt][1]);
            *(float2*)(Cout + (size_t)(rr + 8) * HID_DIM + cc) =
                make_float2(acc[mt][nt][2], acc[mt][nt][3]);
        }
    }
}

// ---------------------------------------------------------------------------
// Elementwise: a = exp(sigmoid(dl) * (-exp(A_log[h]))), bx = B * x_state
// ---------------------------------------------------------------------------
__global__ __launch_bounds__(256) void elemwise_k(const float* __restrict__ A_log)
{
    const int i = (blockIdx.x * 256 + threadIdx.x) << 2;
    float4 xs = *(const float4*)&g_gemm[i];
    float4 Bv = *(const float4*)&g_gemm[SEG + i];
    float4 dl = *(const float4*)&g_gemm[3 * SEG + i];
    const int h = i & (HID_DIM - 1);

    float4 av, bv;
    const float* pxs = (const float*)&xs;
    const float* pB  = (const float*)&Bv;
    const float* pdl = (const float*)&dl;
    float* pav = (float*)&av;
    float* pbv = (float*)&bv;
#pragma unroll
    for (int c = 0; c < 4; c++) {
        float delta = 1.0f / (1.0f + expf(-pdl[c]));
        float negA  = -expf(A_log[h + c]);
        pav[c] = expf(delta * negA);
        pbv[c] = pB[c] * pxs[c];
    }
    *(float4*)&g_a [i] = av;
    *(float4*)&g_bx[i] = bv;
}

// ---------------------------------------------------------------------------
// Chunked scan
// ---------------------------------------------------------------------------
__global__ __launch_bounds__(256) void chunk_reduce_k()
{
    const int h     = blockIdx.x * 256 + threadIdx.x;
    const int chunk = blockIdx.y;
    int idx = chunk * CHUNK_L * HID_DIM + h;

    float ap = 1.0f, bs = 0.0f;
#pragma unroll 8
    for (int l = 0; l < CHUNK_L; l++) {
        float a = g_a[idx];
        float b = g_bx[idx];
        bs = fmaf(a, bs, b);
        ap *= a;
        idx += HID_DIM;
    }
    g_ca[chunk * HID_DIM + h] = ap;
    g_cb[chunk * HID_DIM + h] = bs;
}

__global__ __launch_bounds__(256) void chunk_prefix_k()
{
    const int h = blockIdx.x * 256 + threadIdx.x;
    float hc = 0.0f;
#pragma unroll
    for (int j = 0; j < NCHUNK; j++) {
        g_hinit[j * HID_DIM + h] = hc;
        hc = fmaf(g_ca[j * HID_DIM + h], hc, g_cb[j * HID_DIM + h]);
    }
}

__global__ __launch_bounds__(256) void scan2_k()
{
    const int h     = blockIdx.x * 256 + threadIdx.x;
    const int chunk = blockIdx.y;
    int idx = chunk * CHUNK_L * HID_DIM + h;

    float hc = g_hinit[chunk * HID_DIM + h];
    const float* gC = g_gemm + 2 * SEG;
#pragma unroll 4
    for (int l = 0; l < CHUNK_L; l++) {
        float a = g_a[idx];
        float b = g_bx[idx];
        hc = fmaf(a, hc, b);
        g_y[idx] = gC[idx] * hc;
        idx += HID_DIM;
    }
}

// ---------------------------------------------------------------------------
// Output projection
// ---------------------------------------------------------------------------
__global__ __launch_bounds__(256) void outproj_k(const float* __restrict__ x,
                                                 const float* __restrict__ W_out,
                                                 const float* __restrict__ b_out,
                                                 const float* __restrict__ W_skip,
                                                 float* __restrict__ out)
{
    const int t   = blockIdx.x;
    const int tid = threadIdx.x;

    float acc[NOBJ_DIM];
#pragma unroll
    for (int o = 0; o < NOBJ_DIM; o++) acc[o] = 0.0f;

    const float* yr = g_y + (size_t)t * HID_DIM;
    for (int h = tid; h < HID_DIM; h += 256) {
        float yv = yr[h];
#pragma unroll
        for (int o = 0; o < NOBJ_DIM; o++)
            acc[o] = fmaf(yv, W_out[o * HID_DIM + h], acc[o]);
    }
    const float* xr = x + (size_t)t * OBS_DIM;
    for (int k = tid; k < OBS_DIM; k += 256) {
        float xv = xr[k];
#pragma unroll
        for (int o = 0; o < NOBJ_DIM; o++)
            acc[o] = fmaf(xv, W_skip[o * OBS_DIM + k], acc[o]);
    }

#pragma unroll
    for (int o = 0; o < NOBJ_DIM; o++) {
#pragma unroll
        for (int off = 16; off > 0; off >>= 1)
            acc[o] += __shfl_xor_sync(0xffffffffu, acc[o], off);
    }

    __shared__ float sred[NOBJ_DIM][8];
    const int wid  = tid >> 5;
    const int lane = tid & 31;
    if (lane == 0) {
#pragma unroll
        for (int o = 0; o < NOBJ_DIM; o++) sred[o][wid] = acc[o];
    }
    __syncthreads();
    if (tid < NOBJ_DIM) {
        float s = b_out[tid];
#pragma unroll
        for (int w = 0; w < 8; w++) s += sred[tid][w];
        out[(size_t)t * NOBJ_DIM + tid] = s;
    }
}

// ---------------------------------------------------------------------------
// Launch
// ---------------------------------------------------------------------------
extern "C" void kernel_launch(void* const* d_in, const int* in_sizes, int n_in,
                              void* d_out, int out_size)
{
    const float* x       = (const float*)d_in[0];
    const float* W_in    = (const float*)d_in[1];
    const float* W_B     = (const float*)d_in[2];
    const float* W_C     = (const float*)d_in[3];
    const float* W_delta = (const float*)d_in[4];
    const float* A_log   = (const float*)d_in[5];
    const float* W_out   = (const float*)d_in[6];
    const float* b_out   = (const float*)d_in[7];
    const float* W_skip  = (const float*)d_in[8];
    float* out = (float*)d_out;

    cudaFuncSetAttribute(mma_gemm, cudaFuncAttributeMaxDynamicSharedMemorySize,
                         GEMM_SMEM);

    // bf16 hi/lo splits
    conv_x_k<<<T_DIM * OBS_DIM / 1024, 256>>>(x);
    conv_w_k<<<dim3(HID_DIM * OBS_DIM / 1024, 4), 256>>>(W_in, W_B, W_C, W_delta);

    // Tensor-core (HMMA) split-bf16 GEMM, all 4 planes
    mma_gemm<<<dim3(HID_DIM / BN, T_DIM / BM, 4), 256, GEMM_SMEM>>>();

    elemwise_k<<<SEG / 4 / 256, 256>>>(A_log);

    chunk_reduce_k<<<dim3(HID_DIM / 256, NCHUNK), 256>>>();
    chunk_prefix_k<<<HID_DIM / 256, 256>>>();
    scan2_k<<<dim3(HID_DIM / 256, NCHUNK), 256>>>();

    outproj_k<<<T_DIM, 256>>>(x, W_out, b_out, W_skip, out);
}